// round 1
// baseline (speedup 1.0000x reference)
#include <cuda_runtime.h>

// RNNPool: 8192 windows x 8 steps x E=512 tanh-RNN.
// Each step: h = tanh(x_t @ W_ih^T + h @ W_hh^T + b_ih + b_hh)
// Implemented as 8 chained GEMM+epilogue launches with ping-pong scratch.

#define BM 128
#define BN 128
#define BK 16
#define NWIN 8192
#define E 512

// ping-pong hidden-state scratch (32 MB static, allocation-free)
__device__ float g_h[2][NWIN * E];

__device__ __forceinline__ float tanh_acc(float x) {
    // accurate tanh via exp: tanh(x) = sign(x) * (1 - e)/(1 + e), e = exp(-2|x|)
    float ax = fabsf(x);
    float t  = __expf(-2.0f * ax);
    float r  = (1.0f - t) / (1.0f + t);
    return (x >= 0.0f) ? r : -r;
}

template <bool HAS_H>
__global__ void __launch_bounds__(256, 2) rnn_step(
    const float* __restrict__ Ax,   // x slice: row n at Ax[n*4096], 512 valid cols
    int hin,                        // g_h buffer index for h_prev (ignored if !HAS_H)
    int hout,                       // g_h buffer index for h_out, or -1 -> OutParam
    const float* __restrict__ Wih,  // [512,512] row-major (j, e)
    const float* __restrict__ Whh,  // [512,512] row-major (j, e)
    const float* __restrict__ bih,
    const float* __restrict__ bhh,
    float* __restrict__ OutParam)
{
    __shared__ float As[BK][BM];
    __shared__ float Bs[BK][BN];

    const int tid  = threadIdx.x;
    const int tx   = tid & 15;   // 0..15 column group
    const int ty   = tid >> 4;   // 0..15 row group
    const int row0 = blockIdx.x * BM;  // window tile
    const int col0 = blockIdx.y * BN;  // output-feature tile

    const float* Ah  = HAS_H ? &g_h[hin][0] : nullptr;
    float*       Out = (hout >= 0) ? &g_h[hout][0] : OutParam;

    float acc[8][8];
    #pragma unroll
    for (int i = 0; i < 8; i++)
        #pragma unroll
        for (int j = 0; j < 8; j++) acc[i][j] = 0.0f;

    const int nphase = HAS_H ? 2 : 1;
    for (int phase = 0; phase < nphase; ++phase) {
        const float* A   = phase ? Ah : Ax;
        const int    lda = phase ? 512 : 4096;   // h rows are dense; x rows stride 8*512
        const float* W   = phase ? Whh : Wih;

        for (int kt = 0; kt < E; kt += BK) {
            // Load A tile (128 rows x 16 k) and B tile (128 j x 16 k), transposed to smem.
            // 512 float4 each; 2 per thread.
            #pragma unroll
            for (int v = 0; v < 2; ++v) {
                int g  = tid + v * 256;   // 0..511
                int r  = g >> 2;          // 0..127
                int kv = (g & 3) * 4;     // 0,4,8,12
                float4 fa = *reinterpret_cast<const float4*>(
                    A + (long)(row0 + r) * lda + kt + kv);
                As[kv + 0][r] = fa.x; As[kv + 1][r] = fa.y;
                As[kv + 2][r] = fa.z; As[kv + 3][r] = fa.w;
                float4 fb = *reinterpret_cast<const float4*>(
                    W + (long)(col0 + r) * 512 + kt + kv);
                Bs[kv + 0][r] = fb.x; Bs[kv + 1][r] = fb.y;
                Bs[kv + 2][r] = fb.z; Bs[kv + 3][r] = fb.w;
            }
            __syncthreads();

            #pragma unroll
            for (int k = 0; k < BK; ++k) {
                float a[8], b[8];
                #pragma unroll
                for (int i = 0; i < 8; i++) a[i] = As[k][ty * 8 + i];
                #pragma unroll
                for (int j = 0; j < 8; j++) b[j] = Bs[k][tx * 8 + j];
                #pragma unroll
                for (int i = 0; i < 8; i++)
                    #pragma unroll
                    for (int j = 0; j < 8; j++)
                        acc[i][j] = fmaf(a[i], b[j], acc[i][j]);
            }
            __syncthreads();
        }
    }

    // Epilogue: + bias, tanh, vectorized store
    #pragma unroll
    for (int i = 0; i < 8; i++) {
        int n = row0 + ty * 8 + i;
        #pragma unroll
        for (int jj = 0; jj < 2; jj++) {
            int c = col0 + tx * 8 + jj * 4;
            float4 bi = *reinterpret_cast<const float4*>(bih + c);
            float4 bh = *reinterpret_cast<const float4*>(bhh + c);
            float4 o;
            o.x = tanh_acc(acc[i][jj * 4 + 0] + bi.x + bh.x);
            o.y = tanh_acc(acc[i][jj * 4 + 1] + bi.y + bh.y);
            o.z = tanh_acc(acc[i][jj * 4 + 2] + bi.z + bh.z);
            o.w = tanh_acc(acc[i][jj * 4 + 3] + bi.w + bh.w);
            *reinterpret_cast<float4*>(Out + (long)n * 512 + c) = o;
        }
    }
}

extern "C" void kernel_launch(void* const* d_in, const int* in_sizes, int n_in,
                              void* d_out, int out_size)
{
    const float* x   = (const float*)d_in[0];  // [16,4096,512]
    const float* Wih = (const float*)d_in[1];  // [512,512]
    const float* Whh = (const float*)d_in[2];  // [512,512]
    const float* bih = (const float*)d_in[3];  // [512]
    const float* bhh = (const float*)d_in[4];  // [512]
    float* out = (float*)d_out;                // [16,512,512] == [8192,512]

    dim3 grid(NWIN / BM, E / BN);  // 64 x 4
    for (int t = 0; t < 8; ++t) {
        const float* Axt = x + t * 512;        // row n at Axt[n*4096]
        int hin  = (t == 0) ? -1 : ((t - 1) & 1);
        int hout = (t == 7) ? -1 : (t & 1);
        if (t == 0)
            rnn_step<false><<<grid, 256>>>(Axt, hin, hout, Wih, Whh, bih, bhh, out);
        else
            rnn_step<true><<<grid, 256>>>(Axt, hin, hout, Wih, Whh, bih, bhh, out);
    }
}

// round 4
// speedup vs baseline: 2.5210x; 2.5210x over previous
#include <cuda_runtime.h>
#include <cuda_bf16.h>
#include <cstdint>

// ============================================================================
// RNNPool via mma.sync bf16 split GEMMs (sm_100-compatible PTX path).
// h = tanh(x_t @ Wih^T + h @ Whh^T + b);  fp32 emulated as Ah*Bh + Al*Bh + Ah*Bl
// ============================================================================

#define NWIN  8192
#define E     512
#define NSTEP 8
#define BM    128
#define BN    128

// ---------------- static device scratch (allocation-free) -------------------
__device__ __align__(16) __nv_bfloat16 g_x_hi[NSTEP][NWIN * E];   // 64 MB
__device__ __align__(16) __nv_bfloat16 g_x_lo[NSTEP][NWIN * E];   // 64 MB
__device__ __align__(16) __nv_bfloat16 g_h_hi[2][NWIN * E];
__device__ __align__(16) __nv_bfloat16 g_h_lo[2][NWIN * E];
__device__ __align__(16) __nv_bfloat16 g_W_hi[2][E * E];          // [0]=Wih,[1]=Whh
__device__ __align__(16) __nv_bfloat16 g_W_lo[2][E * E];

// ---------------- smem layout: 2 stages x (Ahi,Alo,Bhi,Blo) -----------------
// tile = 128 rows x 32 bf16, padded to 40 elems (80 B pitch) for ldmatrix.
#define TILE_B   10240              // 128 * 80
#define OFF_ALO  10240
#define OFF_BHI  20480
#define OFF_BLO  30720
#define ST_BYTES 40960
#define SM_BIAS  (2 * ST_BYTES)     // 81920
#define SMEM_TOTAL (SM_BIAS + 512)  // + 128 floats bias

// ---------------- PTX helpers ----------------
__device__ __forceinline__ uint32_t smem_u32(const void* p) {
    uint32_t a;
    asm("{ .reg .u64 t; cvta.to.shared.u64 t, %1; cvt.u32.u64 %0, t; }" : "=r"(a) : "l"(p));
    return a;
}
__device__ __forceinline__ void cp16(uint32_t dst, const void* src) {
    asm volatile("cp.async.cg.shared.global [%0], [%1], 16;" :: "r"(dst), "l"(src));
}
#define CP_COMMIT() asm volatile("cp.async.commit_group;" ::: "memory")
#define CP_WAIT(n)  asm volatile("cp.async.wait_group %0;" :: "n"(n) : "memory")

__device__ __forceinline__ void ldsm4(uint32_t* r, uint32_t addr) {
    asm volatile("ldmatrix.sync.aligned.m8n8.x4.shared.b16 {%0,%1,%2,%3}, [%4];"
                 : "=r"(r[0]), "=r"(r[1]), "=r"(r[2]), "=r"(r[3]) : "r"(addr));
}
__device__ __forceinline__ void mma16816(float* c, const uint32_t* a, uint32_t b0, uint32_t b1) {
    asm volatile(
        "mma.sync.aligned.m16n8k16.row.col.f32.bf16.bf16.f32 "
        "{%0,%1,%2,%3}, {%4,%5,%6,%7}, {%8,%9}, {%0,%1,%2,%3};"
        : "+f"(c[0]), "+f"(c[1]), "+f"(c[2]), "+f"(c[3])
        : "r"(a[0]), "r"(a[1]), "r"(a[2]), "r"(a[3]), "r"(b0), "r"(b1));
}

// ---------------- math helpers ----------------
__device__ __forceinline__ float tanh_acc(float x) {
    float ax = fabsf(x);
    float t  = __expf(-2.0f * ax);
    float r  = (1.0f - t) / (1.0f + t);
    return (x >= 0.0f) ? r : -r;
}
__device__ __forceinline__ void split_bf16(float f, __nv_bfloat16& h, __nv_bfloat16& l) {
    h = __float2bfloat16(f);
    l = __float2bfloat16(f - __bfloat162float(h));
}

// ---------------- conversion pre-passes ----------------
__global__ void convert_x(const float* __restrict__ x) {
    long i = ((long)blockIdx.x * 256 + threadIdx.x) * 4;    // over 16*4096*512
    float4 v = *(const float4*)(x + i);
    long g = i >> 9;             // global seq row 0..65535
    int  e = (int)(i & 511);
    int  t = (int)(g & 7);       // position within window
    long n = g >> 3;             // window index (b*512 + w)
    long o = n * 512 + e;
    float f[4] = {v.x, v.y, v.z, v.w};
    __nv_bfloat16 hb[4], lb[4];
    #pragma unroll
    for (int j = 0; j < 4; ++j) split_bf16(f[j], hb[j], lb[j]);
    *(__nv_bfloat162*)(&g_x_hi[t][o])     = __nv_bfloat162(hb[0], hb[1]);
    *(__nv_bfloat162*)(&g_x_hi[t][o + 2]) = __nv_bfloat162(hb[2], hb[3]);
    *(__nv_bfloat162*)(&g_x_lo[t][o])     = __nv_bfloat162(lb[0], lb[1]);
    *(__nv_bfloat162*)(&g_x_lo[t][o + 2]) = __nv_bfloat162(lb[2], lb[3]);
}
__global__ void convert_w(const float* __restrict__ Wih, const float* __restrict__ Whh) {
    int i = blockIdx.x * 256 + threadIdx.x;                 // over 262144
    split_bf16(Wih[i], g_W_hi[0][i], g_W_lo[0][i]);
    split_bf16(Whh[i], g_W_hi[1][i], g_W_lo[1][i]);
}

// ---------------- main step kernel ----------------
template <bool HAS_H, bool LAST>
__global__ void __launch_bounds__(128, 2) rnn_step_mma(
    int t, int hin, int hout,
    const float* __restrict__ bih, const float* __restrict__ bhh,
    float* __restrict__ out)
{
    extern __shared__ char smem[];
    const uint32_t sbase = smem_u32(smem);
    const int tid  = threadIdx.x;
    const int wid  = tid >> 5;
    const int lane = tid & 31;
    const int row0 = blockIdx.x * BM;
    const int col0 = blockIdx.y * BN;
    const int wm   = (wid & 1) * 64;
    const int wn   = (wid >> 1) * 64;

    float* bias_s = (float*)(smem + SM_BIAS);
    bias_s[tid] = bih[col0 + tid] + bhh[col0 + tid];   // 128 threads, 128 cols

    const int nch = HAS_H ? 32 : 16;

    // ---- chunk loader: 128x32 tiles of Ahi/Alo/Bhi/Blo via cp.async ----
    auto load_chunk = [&](int c, int s) {
        const __nv_bfloat16 *ah, *al, *bh, *bl;
        int k0;
        if (!HAS_H || c < 16) {
            ah = g_x_hi[t]; al = g_x_lo[t];
            bh = g_W_hi[0]; bl = g_W_lo[0];
            k0 = c * 32;
        } else {
            ah = g_h_hi[hin]; al = g_h_lo[hin];
            bh = g_W_hi[1];   bl = g_W_lo[1];
            k0 = (c - 16) * 32;
        }
        uint32_t sb = sbase + s * ST_BYTES;
        #pragma unroll
        for (int i = 0; i < 4; ++i) {
            int idx = tid + i * 128;       // 0..511
            int r   = idx >> 2;            // 0..127
            int q   = idx & 3;             // 16B quarter
            uint32_t off = (uint32_t)(r * 80 + q * 16);
            long ga = (long)(row0 + r) * E + k0 + q * 8;
            long gb = (long)(col0 + r) * E + k0 + q * 8;
            cp16(sb + off,           ah + ga);
            cp16(sb + OFF_ALO + off, al + ga);
            cp16(sb + OFF_BHI + off, bh + gb);
            cp16(sb + OFF_BLO + off, bl + gb);
        }
        CP_COMMIT();
    };

    float acc[4][8][4];
    #pragma unroll
    for (int a = 0; a < 4; ++a)
        #pragma unroll
        for (int b = 0; b < 8; ++b)
            #pragma unroll
            for (int c = 0; c < 4; ++c) acc[a][b][c] = 0.0f;

    load_chunk(0, 0);

    for (int c = 0; c < nch; ++c) {
        const int s = c & 1;
        if (c + 1 < nch) { load_chunk(c + 1, s ^ 1); CP_WAIT(1); }
        else             { CP_WAIT(0); }
        __syncthreads();

        uint32_t sb = sbase + s * ST_BYTES;
        // A ldmatrix addressing: matrix p=lane/8: row += (p&1)*8, k += (p>>1)*8
        const uint32_t arow = wm + (lane & 7) + ((lane >> 3) & 1) * 8;
        const uint32_t akof = ((lane >> 4) & 1) * 8;
        // B: matrix p: row += (p>>1)*8, k += (p&1)*8
        const uint32_t brow = wn + (lane & 7) + ((lane >> 4) & 1) * 8;
        const uint32_t bkof = ((lane >> 3) & 1) * 8;

        #pragma unroll
        for (int kk = 0; kk < 2; ++kk) {
            const uint32_t ko = kk * 16;
            uint32_t ahf[4][4], alf[4][4];
            #pragma unroll
            for (int mt = 0; mt < 4; ++mt) {
                uint32_t ad = sb + (arow + mt * 16) * 80 + (ko + akof) * 2;
                ldsm4(ahf[mt], ad);
                ldsm4(alf[mt], ad + OFF_ALO);
            }
            #pragma unroll
            for (int nt = 0; nt < 4; ++nt) {
                uint32_t bd = sb + OFF_BHI + (brow + nt * 16) * 80 + (ko + bkof) * 2;
                uint32_t bhf[4], blf[4];
                ldsm4(bhf, bd);
                ldsm4(blf, bd + TILE_B);   // BLO = BHI + 10240
                #pragma unroll
                for (int mt = 0; mt < 4; ++mt) {
                    mma16816(acc[mt][2 * nt],     ahf[mt], bhf[0], bhf[1]);
                    mma16816(acc[mt][2 * nt],     alf[mt], bhf[0], bhf[1]);
                    mma16816(acc[mt][2 * nt],     ahf[mt], blf[0], blf[1]);
                    mma16816(acc[mt][2 * nt + 1], ahf[mt], bhf[2], bhf[3]);
                    mma16816(acc[mt][2 * nt + 1], alf[mt], bhf[2], bhf[3]);
                    mma16816(acc[mt][2 * nt + 1], ahf[mt], blf[2], blf[3]);
                }
            }
        }
        __syncthreads();
    }

    // ---- epilogue: bias + tanh; write fp32 out or hi/lo recurrent state ----
    __nv_bfloat16* hh = g_h_hi[hout];
    __nv_bfloat16* hl = g_h_lo[hout];
    #pragma unroll
    for (int mt = 0; mt < 4; ++mt) {
        const long r0 = row0 + wm + mt * 16 + (lane >> 2);
        #pragma unroll
        for (int nt = 0; nt < 8; ++nt) {
            const int cl = wn + nt * 8 + (lane & 3) * 2;   // local col
            const long cg = col0 + cl;
            const float b0 = bias_s[cl], b1 = bias_s[cl + 1];
            float v00 = tanh_acc(acc[mt][nt][0] + b0);
            float v01 = tanh_acc(acc[mt][nt][1] + b1);
            float v10 = tanh_acc(acc[mt][nt][2] + b0);
            float v11 = tanh_acc(acc[mt][nt][3] + b1);
            if (LAST) {
                *(float2*)(out + r0 * E + cg)       = make_float2(v00, v01);
                *(float2*)(out + (r0 + 8) * E + cg) = make_float2(v10, v11);
            } else {
                __nv_bfloat16 h0, l0, h1, l1;
                split_bf16(v00, h0, l0); split_bf16(v01, h1, l1);
                *(__nv_bfloat162*)(hh + r0 * E + cg) = __nv_bfloat162(h0, h1);
                *(__nv_bfloat162*)(hl + r0 * E + cg) = __nv_bfloat162(l0, l1);
                split_bf16(v10, h0, l0); split_bf16(v11, h1, l1);
                *(__nv_bfloat162*)(hh + (r0 + 8) * E + cg) = __nv_bfloat162(h0, h1);
                *(__nv_bfloat162*)(hl + (r0 + 8) * E + cg) = __nv_bfloat162(l0, l1);
            }
        }
    }
}

// ---------------- launch ----------------
extern "C" void kernel_launch(void* const* d_in, const int* in_sizes, int n_in,
                              void* d_out, int out_size)
{
    const float* x   = (const float*)d_in[0];
    const float* Wih = (const float*)d_in[1];
    const float* Whh = (const float*)d_in[2];
    const float* bih = (const float*)d_in[3];
    const float* bhh = (const float*)d_in[4];
    float* out = (float*)d_out;

    // idempotent, capture-safe, called every time (no static guards)
    cudaFuncSetAttribute(rnn_step_mma<false, false>, cudaFuncAttributeMaxDynamicSharedMemorySize, SMEM_TOTAL);
    cudaFuncSetAttribute(rnn_step_mma<true,  false>, cudaFuncAttributeMaxDynamicSharedMemorySize, SMEM_TOTAL);
    cudaFuncSetAttribute(rnn_step_mma<true,  true >, cudaFuncAttributeMaxDynamicSharedMemorySize, SMEM_TOTAL);

    convert_x<<<32768, 256>>>(x);
    convert_w<<<1024, 256>>>(Wih, Whh);

    dim3 grid(NWIN / BM, E / BN);   // (64, 4)
    for (int t = 0; t < NSTEP; ++t) {
        if (t == 0)
            rnn_step_mma<false, false><<<grid, 128, SMEM_TOTAL>>>(0, 0, 0, bih, bhh, out);
        else if (t < 7)
            rnn_step_mma<true, false><<<grid, 128, SMEM_TOTAL>>>(t, (t - 1) & 1, t & 1, bih, bhh, out);
        else
            rnn_step_mma<true, true><<<grid, 128, SMEM_TOTAL>>>(t, (t - 1) & 1, 0, bih, bhh, out);
    }
}